// round 1
// baseline (speedup 1.0000x reference)
#include <cuda_runtime.h>
#include <math.h>

// ---------------------------------------------------------------------------
// TopKRouter: logits = hidden[16384,2048] @ W[64,2048]^T, softmax, top-2,
// weight renorm, z-loss (per-expert variance of logits), load-balance loss
// (CV of gathered-prob mass per expert).
//
// Output layout (float32, concatenated in reference return order):
//   [0,       32768)   expert_weights [T,2]
//   [32768,   65536)   expert_indices [T,2] (as float)
//   [65536, 1114112)   router_logits  [T,64]
//   [1114112]          router_z_loss
//   [1114113]          load_balancing_loss
// ---------------------------------------------------------------------------

#define T_TOK   16384
#define H_DIM   2048
#define E_DIM   64
#define BM      128
#define BK      16
#define AS_LD   132   // padded leading dim (multiple of 4 for float4 reads)
#define BS_LD   68

#define NBLK    (T_TOK / BM)      // 128 GEMM/epilogue blocks

#define W_OFF   0
#define I_OFF   32768
#define L_OFF   65536
#define Z_OFF   1114112
#define LB_OFF  1114113

// Deterministic reduction scratch: per block, 3 arrays of 64 floats
// (sum logits, sum logits^2, sum gathered probs per expert).
__device__ float g_partials[NBLK * 3 * E_DIM];

// ---------------------------------------------------------------------------
// Kernel 1: fp32 SGEMM, 128x64 block tile, 8x4 thread tile, BK=16,
// register-prefetch single-buffer pipeline. Exact fp32 (FFMA) so top-2
// ordering matches the fp32 reference.
// ---------------------------------------------------------------------------
__global__ __launch_bounds__(256, 1)
void gemm_kernel(const float* __restrict__ A,   // [T_TOK, H_DIM]
                 const float* __restrict__ W,   // [E_DIM, H_DIM]
                 float* __restrict__ logits)    // [T_TOK, E_DIM]
{
    __shared__ float As[BK][AS_LD];
    __shared__ float Bs[BK][BS_LD];

    const int tid  = threadIdx.x;
    const int row0 = blockIdx.x * BM;

    const int tx = tid & 15;        // expert group: experts tx*4 .. tx*4+3
    const int ty = tid >> 4;        // token group: tokens  ty*8 .. ty*8+7

    // Global-load assignments (float4 granularity)
    const int fa0 = tid;            // A float4 index 0..255
    const int fa1 = tid + 256;      // A float4 index 256..511
    const int mA0 = fa0 >> 2, kA0 = (fa0 & 3) * 4;
    const int mA1 = fa1 >> 2, kA1 = (fa1 & 3) * 4;
    const int eB  = tid >> 2, kB  = (tid & 3) * 4;

    const float* Arow0 = A + (size_t)(row0 + mA0) * H_DIM;
    const float* Arow1 = A + (size_t)(row0 + mA1) * H_DIM;
    const float* Brow  = W + (size_t)eB * H_DIM;

    float acc[8][4];
#pragma unroll
    for (int i = 0; i < 8; i++)
#pragma unroll
        for (int j = 0; j < 4; j++) acc[i][j] = 0.0f;

    // Prologue: load k-tile 0 into registers
    float4 pa0 = *(const float4*)(Arow0 + 0 + kA0);
    float4 pa1 = *(const float4*)(Arow1 + 0 + kA1);
    float4 pb  = *(const float4*)(Brow  + 0 + kB);

    for (int kt = 0; kt < H_DIM; kt += BK) {
        // Stage registers -> smem (transposed to [k][m])
        As[kA0 + 0][mA0] = pa0.x; As[kA0 + 1][mA0] = pa0.y;
        As[kA0 + 2][mA0] = pa0.z; As[kA0 + 3][mA0] = pa0.w;
        As[kA1 + 0][mA1] = pa1.x; As[kA1 + 1][mA1] = pa1.y;
        As[kA1 + 2][mA1] = pa1.z; As[kA1 + 3][mA1] = pa1.w;
        Bs[kB  + 0][eB ] = pb.x;  Bs[kB  + 1][eB ] = pb.y;
        Bs[kB  + 2][eB ] = pb.z;  Bs[kB  + 3][eB ] = pb.w;
        __syncthreads();

        // Prefetch next k-tile (overlaps with FFMA block below)
        const int ktn = kt + BK;
        if (ktn < H_DIM) {
            pa0 = *(const float4*)(Arow0 + ktn + kA0);
            pa1 = *(const float4*)(Arow1 + ktn + kA1);
            pb  = *(const float4*)(Brow  + ktn + kB);
        }

#pragma unroll
        for (int k = 0; k < BK; k++) {
            float4 a0 = *(const float4*)&As[k][ty * 8];
            float4 a1 = *(const float4*)&As[k][ty * 8 + 4];
            float4 b  = *(const float4*)&Bs[k][tx * 4];
            float av[8] = {a0.x, a0.y, a0.z, a0.w, a1.x, a1.y, a1.z, a1.w};
            float bv[4] = {b.x, b.y, b.z, b.w};
#pragma unroll
            for (int i = 0; i < 8; i++)
#pragma unroll
                for (int j = 0; j < 4; j++)
                    acc[i][j] = fmaf(av[i], bv[j], acc[i][j]);
        }
        __syncthreads();
    }

    // Epilogue: write logits (coalesced float4 per thread-row)
#pragma unroll
    for (int i = 0; i < 8; i++) {
        const int row = row0 + ty * 8 + i;
        float4 v = make_float4(acc[i][0], acc[i][1], acc[i][2], acc[i][3]);
        *(float4*)&logits[(size_t)row * E_DIM + tx * 4] = v;
    }
}

// ---------------------------------------------------------------------------
// Kernel 2: per-token softmax / top-2 / weight renorm + per-block partial
// reductions (deterministic: per-warp register+smem accumulation, fixed-order
// block combine; no float atomics).
// Block = 256 threads = 8 warps; warp w handles 16 consecutive tokens.
// Lane l owns experts l and l+32.
// ---------------------------------------------------------------------------
__global__ __launch_bounds__(256, 1)
void epilogue_kernel(const float* __restrict__ logits,
                     float* __restrict__ out_w,
                     float* __restrict__ out_i)
{
    __shared__ float S1s[8][E_DIM];
    __shared__ float S2s[8][E_DIM];
    __shared__ float Cs[8][E_DIM];

    const int tid = threadIdx.x;
    const int w   = tid >> 5;
    const int l   = tid & 31;
    const unsigned FULL = 0xffffffffu;

    Cs[w][l] = 0.0f; Cs[w][l + 32] = 0.0f;

    float s1a = 0.0f, s1b = 0.0f, s2a = 0.0f, s2b = 0.0f;
    const int tbase = blockIdx.x * 128 + w * 16;

    for (int j = 0; j < 16; j++) {
        const int t = tbase + j;
        const float L0 = logits[(size_t)t * E_DIM + l];
        const float L1 = logits[(size_t)t * E_DIM + 32 + l];

        // warp max over 64 logits
        float m = fmaxf(L0, L1);
#pragma unroll
        for (int o = 16; o > 0; o >>= 1)
            m = fmaxf(m, __shfl_xor_sync(FULL, m, o));

        // sumexp
        float se = expf(L0 - m) + expf(L1 - m);
#pragma unroll
        for (int o = 16; o > 0; o >>= 1)
            se += __shfl_xor_sync(FULL, se, o);

        // --- top-1 (ties -> lower index, matching jax.lax.top_k) ---
        float v1 = L0; int i1 = l;
        if (L1 > L0) { v1 = L1; i1 = l + 32; }
#pragma unroll
        for (int o = 16; o > 0; o >>= 1) {
            float vo = __shfl_xor_sync(FULL, v1, o);
            int   io = __shfl_xor_sync(FULL, i1, o);
            if (vo > v1 || (vo == v1 && io < i1)) { v1 = vo; i1 = io; }
        }
        // --- top-2: mask winner, argmax again ---
        float m0 = (l        == i1) ? -INFINITY : L0;
        float m1 = (l + 32   == i1) ? -INFINITY : L1;
        float v2 = m0; int i2 = l;
        if (m1 > m0) { v2 = m1; i2 = l + 32; }
#pragma unroll
        for (int o = 16; o > 0; o >>= 1) {
            float vo = __shfl_xor_sync(FULL, v2, o);
            int   io = __shfl_xor_sync(FULL, i2, o);
            if (vo > v2 || (vo == v2 && io < i2)) { v2 = vo; i2 = io; }
        }

        const float p1 = expf(v1 - m) / se;
        const float p2 = expf(v2 - m) / se;

        if (l == 0) {
            const float inv = 1.0f / (p1 + p2);
            out_w[(size_t)t * 2 + 0] = p1 * inv;
            out_w[(size_t)t * 2 + 1] = p2 * inv;
            out_i[(size_t)t * 2 + 0] = (float)i1;
            out_i[(size_t)t * 2 + 1] = (float)i2;
            // per-warp gathered-prob accumulation (own smem slice -> no race,
            // fixed token order -> deterministic)
            Cs[w][i1] += p1;
            Cs[w][i2] += p2;
        }

        s1a += L0; s2a = fmaf(L0, L0, s2a);
        s1b += L1; s2b = fmaf(L1, L1, s2b);
    }

    S1s[w][l] = s1a; S1s[w][l + 32] = s1b;
    S2s[w][l] = s2a; S2s[w][l + 32] = s2b;
    __syncthreads();

    // Fixed-order combine of the 8 warps, write block partials
    if (tid < E_DIM) {
        float s1 = 0.0f, s2 = 0.0f, c = 0.0f;
#pragma unroll
        for (int ww = 0; ww < 8; ww++) {
            s1 += S1s[ww][tid];
            s2 += S2s[ww][tid];
            c  += Cs[ww][tid];
        }
        const int b = blockIdx.x;
        g_partials[(b * 3 + 0) * E_DIM + tid] = s1;
        g_partials[(b * 3 + 1) * E_DIM + tid] = s2;
        g_partials[(b * 3 + 2) * E_DIM + tid] = c;
    }
}

// ---------------------------------------------------------------------------
// Kernel 3: fixed-order final reduction + scalar losses.
// ---------------------------------------------------------------------------
__global__ __launch_bounds__(64, 1)
void finalize_kernel(float* __restrict__ out)
{
    __shared__ float sv[E_DIM];
    __shared__ float sf[E_DIM];

    const int e = threadIdx.x;
    float s1 = 0.0f, s2 = 0.0f, c = 0.0f;
    for (int b = 0; b < NBLK; b++) {
        s1 += g_partials[(b * 3 + 0) * E_DIM + e];
        s2 += g_partials[(b * 3 + 1) * E_DIM + e];
        c  += g_partials[(b * 3 + 2) * E_DIM + e];
    }
    const float invT = 1.0f / (float)T_TOK;
    const float mean = s1 * invT;
    sv[e] = s2 * invT - mean * mean;   // per-expert variance
    sf[e] = c * invT;                  // expert_fraction
    __syncthreads();

    if (e == 0) {
        float vsum = 0.0f, fsum = 0.0f;
        for (int i = 0; i < E_DIM; i++) { vsum += sv[i]; fsum += sf[i]; }
        out[Z_OFF] = (vsum / (float)E_DIM) * 0.001f;

        const float meanf = fsum / (float)E_DIM;
        float acc = 0.0f;
        for (int i = 0; i < E_DIM; i++) {
            const float d = sf[i] - meanf;
            acc = fmaf(d, d, acc);
        }
        const float stdv = sqrtf(acc / (float)(E_DIM - 1));  // ddof=1
        out[LB_OFF] = (stdv / (meanf + 1e-8f)) * 0.01f;
    }
}

// ---------------------------------------------------------------------------
extern "C" void kernel_launch(void* const* d_in, const int* in_sizes, int n_in,
                              void* d_out, int out_size)
{
    const float* hs = (const float*)d_in[0];
    const float* W  = (const float*)d_in[1];
    if (n_in >= 2 && in_sizes[0] < in_sizes[1]) {  // defensive input-order guard
        const float* t = hs; hs = W; W = t;
    }

    float* out    = (float*)d_out;
    float* out_w  = out + W_OFF;
    float* out_i  = out + I_OFF;
    float* logits = out + L_OFF;

    gemm_kernel<<<NBLK, 256>>>(hs, W, logits);
    epilogue_kernel<<<NBLK, 256>>>(logits, out_w, out_i);
    finalize_kernel<<<1, 64>>>(out);
}